// round 16
// baseline (speedup 1.0000x reference)
#include <cuda_runtime.h>
#include <cuda_fp16.h>

#define NN 100000
#define NE 1600000
#define NG 1024
#define BSH 6                      // bucket stride shift: 64 slots/node
#define BCAP 64

// ---------------- scratch (static __device__ — no allocation allowed) ----------
__device__ int    g_cnt[NN];          // incoming-edge count per node (excl. self loop)
__device__ float  g_dinv[NN];         // 1/sqrt(deg) (deg incl. self loop)
__device__ int    g_bkt[NN << BSH];   // per-node src buckets (stride 64, 25.6MB)
__device__ __half g_xsh[NN * 4];      // dinv-prescaled input features (fp16, 8B/node)
__device__ __half g_y1h[NN * 64];     // dinv * relu(a1 @ W1 + b1)  (layer-2 pre-scaled)
__device__ __half g_a2h[NN * 64];     // layer-2 pre-projection aggregate (fp16)
__device__ float  g_pool[NG * 128];   // graph-pooled sums
__device__ int    g_gcnt[NG];         // nodes per graph
__device__ int    g_is64;             // index dtype flag

// ---------------- index dtype handling -----------------------------------------
__device__ __forceinline__ int ld_idx(const void* p, long long i, int is64) {
    return is64 ? (int)((const long long*)p)[i] : ((const int*)p)[i];
}

// ---------------- init + dtype detect --------------------------------------------
__global__ void k_zero(const unsigned int* w) {
    int i = blockIdx.x * blockDim.x + threadIdx.x;
    if (i == 0) {
        int is64 = 1;
        #pragma unroll 1
        for (int k = 0; k < 256; k++) {
            if (w[2 * k + 1] != 0u) { is64 = 0; break; }
        }
        g_is64 = is64;
    }
    int4 z = make_int4(0, 0, 0, 0);
    if (i < 25000) ((int4*)g_cnt)[i] = z;
    if (i < 32768) ((int4*)g_pool)[i] = z;
    if (i < 256)   ((int4*)g_gcnt)[i] = z;
}

// ---------------- one-pass CSR: count + bucket-fill (8 edges/thread) -------------
__global__ void k_countfill(const void* ei, int E) {
    int e8 = blockIdx.x * blockDim.x + threadIdx.x;
    int e = e8 * 8;
    if (e >= E) return;
    cudaGridDependencySynchronize();     // wait for k_zero (g_cnt = 0)
    int is64 = g_is64;
    if (e + 7 < E) {
        int s[8], d[8];
        if (is64) {
            const longlong2* sp = (const longlong2*)ei;
            const longlong2* dp = (const longlong2*)((const long long*)ei + E);
            #pragma unroll
            for (int q = 0; q < 4; q++) {
                longlong2 sv = __ldcs(sp + e8 * 4 + q);
                longlong2 dv = __ldcs(dp + e8 * 4 + q);
                s[2 * q] = (int)sv.x; s[2 * q + 1] = (int)sv.y;
                d[2 * q] = (int)dv.x; d[2 * q + 1] = (int)dv.y;
            }
        } else {
            #pragma unroll
            for (int q = 0; q < 2; q++) {
                int4 sv = __ldcs((const int4*)ei + e8 * 2 + q);
                int4 dv = __ldcs((const int4*)((const int*)ei + E) + e8 * 2 + q);
                s[4 * q] = sv.x; s[4 * q + 1] = sv.y; s[4 * q + 2] = sv.z; s[4 * q + 3] = sv.w;
                d[4 * q] = dv.x; d[4 * q + 1] = dv.y; d[4 * q + 2] = dv.z; d[4 * q + 3] = dv.w;
            }
        }
        int r[8];
        #pragma unroll
        for (int q = 0; q < 8; q++) r[q] = atomicAdd(&g_cnt[d[q]], 1);
        #pragma unroll
        for (int q = 0; q < 8; q++)
            if (r[q] < BCAP) __stcg(&g_bkt[(d[q] << BSH) + r[q]], s[q]);
    } else {
        for (int q = e; q < E; q++) {
            int sq = ld_idx(ei, q, is64);
            int dq = ld_idx(ei, (long long)E + q, is64);
            int r = atomicAdd(&g_cnt[dq], 1);
            if (r < BCAP) __stcg(&g_bkt[(dq << BSH) + r], sq);
        }
    }
}

// ---------------- prep: dinv + dinv-prescaled x (fp16) ----------------------------
__global__ void k_prep(const float* __restrict__ x, int n) {
    int i = blockIdx.x * blockDim.x + threadIdx.x;
    if (i >= n) return;
    float4 xi = ((const float4*)x)[i];       // input buffer: safe pre-sync
    cudaGridDependencySynchronize();         // wait for k_countfill (g_cnt final)
    float dn = rsqrtf((float)(g_cnt[i] + 1));   // +1 = self loop
    g_dinv[i] = dn;
    __half2 lo = __floats2half2_rn(dn * xi.x, dn * xi.y);
    __half2 hi = __floats2half2_rn(dn * xi.z, dn * xi.w);
    uint2 st;
    st.x = *(unsigned*)&lo; st.y = *(unsigned*)&hi;
    ((uint2*)g_xsh)[i] = st;
}

// ---------------- fused layer 1 (persistent): gather + W1 + relu ------------------
// 8 lanes per node, grid-stride over 32-node tiles. W1 staged once per block.
__global__ void k_l1(const float* __restrict__ W1, const float* __restrict__ b1, int n) {
    __shared__ float sW[256];
    __shared__ float sb[64];
    int t = threadIdx.x;  // 256
    sW[t] = W1[t];                            // input buffers: safe pre-sync
    if (t < 64) sb[t] = b1[t];
    __syncthreads();
    cudaGridDependencySynchronize();          // wait for k_prep (xs, dinv)
    int nl = t >> 3;           // node within tile (0..31)
    int sub = t & 7;           // lane within node group
    const uint2* __restrict__ xs = (const uint2*)g_xsh;

    for (int base = blockIdx.x * 32; base < n; base += gridDim.x * 32) {
        int i = base + nl;
        if (i >= n) continue;

        float ax = 0.0f, ay = 0.0f, az = 0.0f, aw = 0.0f;
        int b = i << BSH;
        int c = g_cnt[i]; if (c > BCAP) c = BCAP;
        int e = b + c;
        int j0 = b + 2 * sub;
        for (; j0 + 1 < e; j0 += 16) {
            int2 s2 = *(const int2*)&g_bkt[j0];   // one LDG.64 = 2 edge ids
            uint2 u0 = __ldg(xs + s2.x);
            uint2 u1 = __ldg(xs + s2.y);
            float2 a0 = __half22float2(*(__half2*)&u0.x);
            float2 b0 = __half22float2(*(__half2*)&u0.y);
            float2 a1 = __half22float2(*(__half2*)&u1.x);
            float2 b1v = __half22float2(*(__half2*)&u1.y);
            ax += a0.x + a1.x; ay += a0.y + a1.y;
            az += b0.x + b1v.x; aw += b0.y + b1v.y;
        }
        if (j0 < e) {                             // single tail edge
            uint2 u = __ldg(xs + g_bkt[j0]);
            float2 a0 = __half22float2(*(__half2*)&u.x);
            float2 b0 = __half22float2(*(__half2*)&u.y);
            ax += a0.x; ay += a0.y; az += b0.x; aw += b0.y;
        }
        if (sub == 0) {            // self term (already dinv-scaled), add once
            uint2 u = xs[i];
            float2 a0 = __half22float2(*(__half2*)&u.x);
            float2 b0 = __half22float2(*(__half2*)&u.y);
            ax += a0.x; ay += a0.y; az += b0.x; aw += b0.y;
        }
        // reduce across the 8-lane group (all lanes end with full sum)
        #pragma unroll
        for (int o = 1; o < 8; o <<= 1) {
            ax += __shfl_xor_sync(0xffffffffu, ax, o);
            ay += __shfl_xor_sync(0xffffffffu, ay, o);
            az += __shfl_xor_sync(0xffffffffu, az, o);
            aw += __shfl_xor_sync(0xffffffffu, aw, o);
        }
        float dn = g_dinv[i];
        ax *= dn; ay *= dn; az *= dn; aw *= dn;

        uint4 st;
        unsigned* sp = (unsigned*)&st;
        #pragma unroll
        for (int p = 0; p < 4; p++) {
            int f = sub * 8 + p * 2;
            float v0 = fmaf(ax, sW[f],     fmaf(ay, sW[64 + f],     fmaf(az, sW[128 + f],     aw * sW[192 + f])))     + sb[f];
            float v1 = fmaf(ax, sW[f + 1], fmaf(ay, sW[64 + f + 1], fmaf(az, sW[128 + f + 1], aw * sW[192 + f + 1]))) + sb[f + 1];
            __half2 h = __floats2half2_rn(fmaxf(v0, 0.0f) * dn, fmaxf(v1, 0.0f) * dn);
            sp[p] = *(unsigned*)&h;
        }
        ((uint4*)(g_y1h + i * 64 + sub * 8))[0] = st;
    }
}

// ---------------- layer 2 (persistent): gather-sum in 64-dim fp16 space ----------
// blockDim (32,16); grid-stride over 16-node tiles.
__global__ void k_agg2(int n) {
    cudaGridDependencySynchronize();          // wait for k_l1 (y1h)
    int t = threadIdx.x;   // 0..31
    const __half2* __restrict__ y1 = (const __half2*)g_y1h;
    for (int base = blockIdx.x * 16; base < n; base += gridDim.x * 16) {
        int node = base + threadIdx.y;
        if (node >= n) continue;
        float2 acc = __half22float2(y1[(node << 5) + t]);   // self term (pre-scaled)
        float2 acc2; acc2.x = 0.0f; acc2.y = 0.0f;
        int b = node << BSH;
        int c = g_cnt[node]; if (c > BCAP) c = BCAP;
        int e = b + c;
        int j = b;
        for (; j + 7 < e; j += 8) {
            int s0 = g_bkt[j],     s1 = g_bkt[j + 1];
            int s2 = g_bkt[j + 2], s3 = g_bkt[j + 3];
            int s4 = g_bkt[j + 4], s5 = g_bkt[j + 5];
            int s6 = g_bkt[j + 6], s7 = g_bkt[j + 7];
            float2 f0 = __half22float2(__ldg(y1 + (s0 << 5) + t));
            float2 f1 = __half22float2(__ldg(y1 + (s1 << 5) + t));
            float2 f2 = __half22float2(__ldg(y1 + (s2 << 5) + t));
            float2 f3 = __half22float2(__ldg(y1 + (s3 << 5) + t));
            float2 f4 = __half22float2(__ldg(y1 + (s4 << 5) + t));
            float2 f5 = __half22float2(__ldg(y1 + (s5 << 5) + t));
            float2 f6 = __half22float2(__ldg(y1 + (s6 << 5) + t));
            float2 f7 = __half22float2(__ldg(y1 + (s7 << 5) + t));
            acc.x  += (f0.x + f1.x) + (f2.x + f3.x);
            acc.y  += (f0.y + f1.y) + (f2.y + f3.y);
            acc2.x += (f4.x + f5.x) + (f6.x + f7.x);
            acc2.y += (f4.y + f5.y) + (f6.y + f7.y);
        }
        for (; j < e; j++) {
            float2 f = __half22float2(__ldg(y1 + (g_bkt[j] << 5) + t));
            acc.x += f.x; acc.y += f.y;
        }
        acc.x += acc2.x; acc.y += acc2.y;
        float dn = g_dinv[node];
        ((__half2*)g_a2h)[(node << 5) + t] = __floats2half2_rn(acc.x * dn, acc.y * dn);
    }
}

// ---------------- y2 = relu(a2 @ W2 + b2) via HMMA, fused mean-pool --------------
#define MB 64
#define APAD 72
#define CPAD 132
__global__ void k_gemm2pool(const float* __restrict__ W2, const float* __restrict__ b2,
                            const void* __restrict__ batch, int n, int nTiles) {
    __shared__ __align__(16) __half sW2T[128 * APAD];                 // 18432 B, persists
    __shared__ __align__(16) unsigned char sU[MB * CPAD * 2];        // union: sA / sC
    __shared__ int sB[MB];
    __half* sA = (__half*)sU;          // [64][APAD] fp16 a2 tile
    __half* sC = (__half*)sU;          // [64][CPAD] fp16 y2 staging (raw, pre-bias)
    int t = threadIdx.x;  // 256
    int lane = t & 31, w = t >> 5;
    int is64 = g_is64;

    // prologue: W2 conversion (input buffer, safe before grid-dep sync)
    for (int i = t; i < 64 * 128; i += 256) {
        int k = i >> 7, nn_ = i & 127;
        sW2T[nn_ * APAD + k] = __float2half(W2[i]);
    }

    int ng = w >> 1, fh = w & 1;
    int g = lane >> 2, tt = lane & 3;
    int tx = t & 31;
    int ty = t >> 5;
    float bias0 = b2[tx * 4], bias1 = b2[tx * 4 + 1];
    float bias2 = b2[tx * 4 + 2], bias3 = b2[tx * 4 + 3];
    __syncthreads();
    cudaGridDependencySynchronize();   // wait for k_agg2 (a2h)

    for (int tile = blockIdx.x; tile < nTiles; tile += gridDim.x) {
        int base = tile * MB;
        const unsigned* a2u = (const unsigned*)g_a2h;
        for (int i = t; i < MB * 32; i += 256) {
            int nl = i >> 5, c = i & 31;
            int nt = base + nl;
            unsigned v = (nt < n) ? a2u[nt * 32 + c] : 0u;
            *(unsigned*)&sA[nl * APAD + 2 * c] = v;
        }
        if (t < MB) {
            int nt = base + t;
            sB[t] = (nt < n) ? ld_idx(batch, nt, is64) : -1;
        }
        __syncthreads();

        float acc[8][4];
        #pragma unroll
        for (int nt = 0; nt < 8; nt++)
            #pragma unroll
            for (int q = 0; q < 4; q++) acc[nt][q] = 0.0f;

        #pragma unroll
        for (int ks = 0; ks < 4; ks++) {
            int k0 = ks * 16 + 2 * tt;
            const __half* arow0 = &sA[(ng * 16 + g) * APAD + k0];
            const __half* arow1 = arow0 + 8 * APAD;
            unsigned a0 = *(const unsigned*)arow0;
            unsigned a1 = *(const unsigned*)arow1;
            unsigned a2_ = *(const unsigned*)(arow0 + 8);
            unsigned a3 = *(const unsigned*)(arow1 + 8);
            #pragma unroll
            for (int nt = 0; nt < 8; nt++) {
                const __half* brow = &sW2T[(fh * 64 + nt * 8 + g) * APAD + k0];
                unsigned b0 = *(const unsigned*)brow;
                unsigned b1 = *(const unsigned*)(brow + 8);
                asm volatile(
                    "mma.sync.aligned.m16n8k16.row.col.f32.f16.f16.f32 "
                    "{%0,%1,%2,%3}, {%4,%5,%6,%7}, {%8,%9}, {%0,%1,%2,%3};"
                    : "+f"(acc[nt][0]), "+f"(acc[nt][1]), "+f"(acc[nt][2]), "+f"(acc[nt][3])
                    : "r"(a0), "r"(a1), "r"(a2_), "r"(a3), "r"(b0), "r"(b1));
            }
        }
        __syncthreads();

        #pragma unroll
        for (int nt = 0; nt < 8; nt++) {
            int row = ng * 16 + g;
            int col = fh * 64 + nt * 8 + 2 * tt;
            __half2 lo = __floats2half2_rn(acc[nt][0], acc[nt][1]);
            __half2 hi = __floats2half2_rn(acc[nt][2], acc[nt][3]);
            *(__half2*)&sC[row * CPAD + col] = lo;
            *(__half2*)&sC[(row + 8) * CPAD + col] = hi;
        }
        __syncthreads();

        int cur = -1;
        float run0 = 0, run1 = 0, run2 = 0, run3 = 0;
        #pragma unroll
        for (int q = 0; q < 8; q++) {
            int nl = ty * 8 + q;
            int gb = sB[nl];
            float2 v01 = __half22float2(*(const __half2*)&sC[nl * CPAD + 4 * tx]);
            float2 v23 = __half22float2(*(const __half2*)&sC[nl * CPAD + 4 * tx + 2]);
            float y0 = (gb >= 0) ? fmaxf(v01.x + bias0, 0.0f) : 0.0f;
            float y1v = (gb >= 0) ? fmaxf(v01.y + bias1, 0.0f) : 0.0f;
            float y2v = (gb >= 0) ? fmaxf(v23.x + bias2, 0.0f) : 0.0f;
            float y3 = (gb >= 0) ? fmaxf(v23.y + bias3, 0.0f) : 0.0f;
            if (gb != cur) {
                if (cur >= 0) {
                    float* p = &g_pool[cur * 128 + tx * 4];
                    atomicAdd(p, run0); atomicAdd(p + 1, run1);
                    atomicAdd(p + 2, run2); atomicAdd(p + 3, run3);
                }
                cur = gb; run0 = y0; run1 = y1v; run2 = y2v; run3 = y3;
            } else {
                run0 += y0; run1 += y1v; run2 += y2v; run3 += y3;
            }
        }
        if (cur >= 0) {
            float* p = &g_pool[cur * 128 + tx * 4];
            atomicAdd(p, run0); atomicAdd(p + 1, run1);
            atomicAdd(p + 2, run2); atomicAdd(p + 3, run3);
        }

        if (t == 0) {
            int rc = 0, cg = -1;
            for (int q = 0; q < MB; q++) {
                int gb = sB[q];
                if (gb != cg) {
                    if (cg >= 0) atomicAdd(&g_gcnt[cg], rc);
                    cg = gb; rc = (gb >= 0) ? 1 : 0;
                } else if (gb >= 0) rc++;
            }
            if (cg >= 0) atomicAdd(&g_gcnt[cg], rc);
        }
        __syncthreads();
    }
}

// ---------------- head: mean, fc1+relu, fc2 --------------------------------------
__global__ void k_head(const float* __restrict__ fc1W, const float* __restrict__ fc1b,
                       const float* __restrict__ fc2W, const float* __restrict__ fc2b,
                       float* __restrict__ out) {
    cudaGridDependencySynchronize();   // wait for k_gemm2pool (pool, gcnt)
    int g = blockIdx.x;
    int t = threadIdx.x;  // 128
    __shared__ float sv[128];
    __shared__ float red[64];
    float denom = fmaxf((float)g_gcnt[g], 1.0f);
    sv[t] = g_pool[g * 128 + t] / denom;
    __syncthreads();
    if (t < 64) {
        float a = fc1b[t];
        #pragma unroll 8
        for (int k = 0; k < 128; k++) a = fmaf(sv[k], fc1W[k * 64 + t], a);
        red[t] = fmaxf(a, 0.0f) * fc2W[t];
    }
    __syncthreads();
    if (t < 32) {
        float v = red[t] + red[t + 32];
        #pragma unroll
        for (int o = 16; o > 0; o >>= 1) v += __shfl_down_sync(0xffffffffu, v, o);
        if (t == 0) out[g] = v + fc2b[0];
    }
}

// ---------------- launch ----------------------------------------------------------
template <typename F, typename... Args>
static inline void launch_pdl(F f, dim3 grid, dim3 block, Args... args) {
    cudaLaunchConfig_t cfg = {};
    cfg.gridDim = grid;
    cfg.blockDim = block;
    cfg.stream = 0;
    cudaLaunchAttribute attr;
    attr.id = cudaLaunchAttributeProgrammaticStreamSerialization;
    attr.val.programmaticStreamSerializationAllowed = 1;
    cfg.attrs = &attr;
    cfg.numAttrs = 1;
    cudaLaunchKernelEx(&cfg, f, args...);
}

extern "C" void kernel_launch(void* const* d_in, const int* in_sizes, int n_in,
                              void* d_out, int out_size) {
    const float* x     = (const float*)d_in[0];
    const void*  ei    = d_in[1];
    const void*  batch = d_in[2];
    const float* W1    = (const float*)d_in[3];
    const float* b1    = (const float*)d_in[4];
    const float* W2    = (const float*)d_in[5];
    const float* b2    = (const float*)d_in[6];
    const float* fc1W  = (const float*)d_in[7];
    const float* fc1b  = (const float*)d_in[8];
    const float* fc2W  = (const float*)d_in[9];
    const float* fc2b  = (const float*)d_in[10];
    float* out = (float*)d_out;

    int N = in_sizes[0] / 4;   // 100000
    int E = in_sizes[1] / 2;   // 1600000

    k_zero<<<(32768 + 255) / 256, 256>>>((const unsigned int*)ei);

    int ep8 = (E + 7) / 8;  // edge octets
    launch_pdl(k_countfill, dim3((ep8 + 255) / 256), dim3(256), ei, E);

    launch_pdl(k_prep, dim3((N + 255) / 256), dim3(256), x, N);

    launch_pdl(k_l1, dim3(888), dim3(256), W1, b1, N);       // persistent, ~6/SM

    launch_pdl(k_agg2, dim3(592), dim3(32, 16), N);          // persistent, ~4/SM

    int nTiles = (N + MB - 1) / MB;        // 1563
    launch_pdl(k_gemm2pool, dim3(521), dim3(256), W2, b2, batch, N, nTiles);

    launch_pdl(k_head, dim3(NG), dim3(128), fc1W, fc1b, fc2W, fc2b, out);
}

// round 17
// speedup vs baseline: 1.0435x; 1.0435x over previous
#include <cuda_runtime.h>
#include <cuda_fp16.h>

#define NN 100000
#define NE 1600000
#define NG 1024
#define BSH 6                      // bucket stride shift: 64 slots/node
#define BCAP 64

// ---------------- scratch (static __device__ — no allocation allowed) ----------
__device__ int    g_cnt[NN];          // incoming-edge count per node (excl. self loop)
__device__ float  g_dinv[NN];         // 1/sqrt(deg) (deg incl. self loop)
__device__ int    g_bkt[NN << BSH];   // per-node src buckets (stride 64, 25.6MB)
__device__ __half g_xsh[NN * 4];      // dinv-prescaled input features (fp16, 8B/node)
__device__ __half g_y1h[NN * 64];     // dinv * relu(a1 @ W1 + b1)  (layer-2 pre-scaled)
__device__ __half g_a2h[NN * 64];     // layer-2 pre-projection aggregate (fp16)
__device__ float  g_pool[NG * 128];   // graph-pooled sums
__device__ int    g_gcnt[NG];         // nodes per graph
__device__ int    g_is64;             // index dtype flag

// ---------------- index dtype handling -----------------------------------------
__device__ __forceinline__ int ld_idx(const void* p, long long i, int is64) {
    return is64 ? (int)((const long long*)p)[i] : ((const int*)p)[i];
}

// ---------------- init + dtype detect --------------------------------------------
__global__ void k_zero(const unsigned int* w) {
    int i = blockIdx.x * blockDim.x + threadIdx.x;
    if (i == 0) {
        int is64 = 1;
        #pragma unroll 1
        for (int k = 0; k < 256; k++) {
            if (w[2 * k + 1] != 0u) { is64 = 0; break; }
        }
        g_is64 = is64;
    }
    int4 z = make_int4(0, 0, 0, 0);
    if (i < 25000) ((int4*)g_cnt)[i] = z;
    if (i < 32768) ((int4*)g_pool)[i] = z;
    if (i < 256)   ((int4*)g_gcnt)[i] = z;
}

// ---------------- one-pass CSR: count + bucket-fill (4 edges/thread) -------------
__global__ void k_countfill(const void* ei, int E) {
    int e4 = blockIdx.x * blockDim.x + threadIdx.x;
    int e = e4 * 4;
    if (e >= E) return;
    cudaGridDependencySynchronize();     // wait for k_zero (g_cnt = 0)
    int is64 = g_is64;
    if (e + 3 < E) {
        int s0, s1, s2, s3, d0, d1, d2, d3;
        if (is64) {
            const longlong2* sp = (const longlong2*)ei;
            const longlong2* dp = (const longlong2*)((const long long*)ei + E);
            longlong2 sa = __ldcs(sp + e4 * 2), sb = __ldcs(sp + e4 * 2 + 1);
            longlong2 da = __ldcs(dp + e4 * 2), db = __ldcs(dp + e4 * 2 + 1);
            s0 = (int)sa.x; s1 = (int)sa.y; s2 = (int)sb.x; s3 = (int)sb.y;
            d0 = (int)da.x; d1 = (int)da.y; d2 = (int)db.x; d3 = (int)db.y;
        } else {
            int4 sv = __ldcs((const int4*)ei + e4);
            int4 dv = __ldcs((const int4*)((const int*)ei + E) + e4);
            s0 = sv.x; s1 = sv.y; s2 = sv.z; s3 = sv.w;
            d0 = dv.x; d1 = dv.y; d2 = dv.z; d3 = dv.w;
        }
        int r0 = atomicAdd(&g_cnt[d0], 1);
        int r1 = atomicAdd(&g_cnt[d1], 1);
        int r2 = atomicAdd(&g_cnt[d2], 1);
        int r3 = atomicAdd(&g_cnt[d3], 1);
        if (r0 < BCAP) __stcg(&g_bkt[(d0 << BSH) + r0], s0);
        if (r1 < BCAP) __stcg(&g_bkt[(d1 << BSH) + r1], s1);
        if (r2 < BCAP) __stcg(&g_bkt[(d2 << BSH) + r2], s2);
        if (r3 < BCAP) __stcg(&g_bkt[(d3 << BSH) + r3], s3);
    } else {
        for (int q = e; q < E; q++) {
            int sq = ld_idx(ei, q, is64);
            int dq = ld_idx(ei, (long long)E + q, is64);
            int r = atomicAdd(&g_cnt[dq], 1);
            if (r < BCAP) __stcg(&g_bkt[(dq << BSH) + r], sq);
        }
    }
}

// ---------------- prep: dinv + dinv-prescaled x (fp16) ----------------------------
__global__ void k_prep(const float* __restrict__ x, int n) {
    int i = blockIdx.x * blockDim.x + threadIdx.x;
    if (i >= n) return;
    float4 xi = ((const float4*)x)[i];       // input buffer: safe pre-sync
    cudaGridDependencySynchronize();         // wait for k_countfill (g_cnt final)
    float dn = rsqrtf((float)(g_cnt[i] + 1));   // +1 = self loop
    g_dinv[i] = dn;
    __half2 lo = __floats2half2_rn(dn * xi.x, dn * xi.y);
    __half2 hi = __floats2half2_rn(dn * xi.z, dn * xi.w);
    uint2 st;
    st.x = *(unsigned*)&lo; st.y = *(unsigned*)&hi;
    ((uint2*)g_xsh)[i] = st;
}

// ---------------- fused layer 1 (persistent): gather + W1 + relu ------------------
// 8 lanes per node, grid-stride over 32-node tiles. W1 staged once per block.
__global__ void k_l1(const float* __restrict__ W1, const float* __restrict__ b1, int n) {
    __shared__ float sW[256];
    __shared__ float sb[64];
    int t = threadIdx.x;  // 256
    sW[t] = W1[t];                            // input buffers: safe pre-sync
    if (t < 64) sb[t] = b1[t];
    __syncthreads();
    cudaGridDependencySynchronize();          // wait for k_prep (xs, dinv)
    int nl = t >> 3;           // node within tile (0..31)
    int sub = t & 7;           // lane within node group
    const uint2* __restrict__ xs = (const uint2*)g_xsh;

    for (int base = blockIdx.x * 32; base < n; base += gridDim.x * 32) {
        int i = base + nl;
        if (i >= n) continue;

        float ax = 0.0f, ay = 0.0f, az = 0.0f, aw = 0.0f;
        int b = i << BSH;
        int c = g_cnt[i]; if (c > BCAP) c = BCAP;
        int e = b + c;
        int j0 = b + 2 * sub;
        for (; j0 + 1 < e; j0 += 16) {
            int2 s2 = *(const int2*)&g_bkt[j0];   // one LDG.64 = 2 edge ids
            uint2 u0 = __ldg(xs + s2.x);
            uint2 u1 = __ldg(xs + s2.y);
            float2 a0 = __half22float2(*(__half2*)&u0.x);
            float2 b0 = __half22float2(*(__half2*)&u0.y);
            float2 a1 = __half22float2(*(__half2*)&u1.x);
            float2 b1v = __half22float2(*(__half2*)&u1.y);
            ax += a0.x + a1.x; ay += a0.y + a1.y;
            az += b0.x + b1v.x; aw += b0.y + b1v.y;
        }
        if (j0 < e) {                             // single tail edge
            uint2 u = __ldg(xs + g_bkt[j0]);
            float2 a0 = __half22float2(*(__half2*)&u.x);
            float2 b0 = __half22float2(*(__half2*)&u.y);
            ax += a0.x; ay += a0.y; az += b0.x; aw += b0.y;
        }
        if (sub == 0) {            // self term (already dinv-scaled), add once
            uint2 u = xs[i];
            float2 a0 = __half22float2(*(__half2*)&u.x);
            float2 b0 = __half22float2(*(__half2*)&u.y);
            ax += a0.x; ay += a0.y; az += b0.x; aw += b0.y;
        }
        // reduce across the 8-lane group (all lanes end with full sum)
        #pragma unroll
        for (int o = 1; o < 8; o <<= 1) {
            ax += __shfl_xor_sync(0xffffffffu, ax, o);
            ay += __shfl_xor_sync(0xffffffffu, ay, o);
            az += __shfl_xor_sync(0xffffffffu, az, o);
            aw += __shfl_xor_sync(0xffffffffu, aw, o);
        }
        float dn = g_dinv[i];
        ax *= dn; ay *= dn; az *= dn; aw *= dn;

        uint4 st;
        unsigned* sp = (unsigned*)&st;
        #pragma unroll
        for (int p = 0; p < 4; p++) {
            int f = sub * 8 + p * 2;
            float v0 = fmaf(ax, sW[f],     fmaf(ay, sW[64 + f],     fmaf(az, sW[128 + f],     aw * sW[192 + f])))     + sb[f];
            float v1 = fmaf(ax, sW[f + 1], fmaf(ay, sW[64 + f + 1], fmaf(az, sW[128 + f + 1], aw * sW[192 + f + 1]))) + sb[f + 1];
            __half2 h = __floats2half2_rn(fmaxf(v0, 0.0f) * dn, fmaxf(v1, 0.0f) * dn);
            sp[p] = *(unsigned*)&h;
        }
        ((uint4*)(g_y1h + i * 64 + sub * 8))[0] = st;
    }
}

// ---------------- layer 2: unweighted gather-sum in 64-dim fp16 space ------------
__global__ void k_agg2(int n) {
    cudaGridDependencySynchronize();          // wait for k_l1 (y1h)
    int node = blockIdx.x * 16 + threadIdx.y;
    if (node >= n) return;
    int t = threadIdx.x;   // 0..31
    const __half2* __restrict__ y1 = (const __half2*)g_y1h;
    float2 acc = __half22float2(y1[(node << 5) + t]);   // self term (pre-scaled)
    float2 acc2; acc2.x = 0.0f; acc2.y = 0.0f;
    int b = node << BSH;
    int c = g_cnt[node]; if (c > BCAP) c = BCAP;
    int e = b + c;
    int j = b;
    for (; j + 7 < e; j += 8) {
        int s0 = g_bkt[j],     s1 = g_bkt[j + 1];
        int s2 = g_bkt[j + 2], s3 = g_bkt[j + 3];
        int s4 = g_bkt[j + 4], s5 = g_bkt[j + 5];
        int s6 = g_bkt[j + 6], s7 = g_bkt[j + 7];
        float2 f0 = __half22float2(__ldg(y1 + (s0 << 5) + t));
        float2 f1 = __half22float2(__ldg(y1 + (s1 << 5) + t));
        float2 f2 = __half22float2(__ldg(y1 + (s2 << 5) + t));
        float2 f3 = __half22float2(__ldg(y1 + (s3 << 5) + t));
        float2 f4 = __half22float2(__ldg(y1 + (s4 << 5) + t));
        float2 f5 = __half22float2(__ldg(y1 + (s5 << 5) + t));
        float2 f6 = __half22float2(__ldg(y1 + (s6 << 5) + t));
        float2 f7 = __half22float2(__ldg(y1 + (s7 << 5) + t));
        acc.x  += (f0.x + f1.x) + (f2.x + f3.x);
        acc.y  += (f0.y + f1.y) + (f2.y + f3.y);
        acc2.x += (f4.x + f5.x) + (f6.x + f7.x);
        acc2.y += (f4.y + f5.y) + (f6.y + f7.y);
    }
    for (; j < e; j++) {
        float2 f = __half22float2(__ldg(y1 + (g_bkt[j] << 5) + t));
        acc.x += f.x; acc.y += f.y;
    }
    acc.x += acc2.x; acc.y += acc2.y;
    float dn = g_dinv[node];
    ((__half2*)g_a2h)[(node << 5) + t] = __floats2half2_rn(acc.x * dn, acc.y * dn);
}

// ---------------- y2 = relu(a2 @ W2 + b2) via HMMA, fused mean-pool --------------
#define MB 64
#define APAD 72
#define CPAD 132
__global__ void k_gemm2pool(const float* __restrict__ W2, const float* __restrict__ b2,
                            const void* __restrict__ batch, int n, int nTiles) {
    __shared__ __align__(16) __half sW2T[128 * APAD];                 // 18432 B, persists
    __shared__ __align__(16) unsigned char sU[MB * CPAD * 2];        // union: sA / sC
    __shared__ int sB[MB];
    __half* sA = (__half*)sU;          // [64][APAD] fp16 a2 tile
    __half* sC = (__half*)sU;          // [64][CPAD] fp16 y2 staging (raw, pre-bias)
    int t = threadIdx.x;  // 256
    int lane = t & 31, w = t >> 5;
    int is64 = g_is64;

    // prologue: W2 conversion (input buffer, safe before grid-dep sync)
    for (int i = t; i < 64 * 128; i += 256) {
        int k = i >> 7, nn_ = i & 127;
        sW2T[nn_ * APAD + k] = __float2half(W2[i]);
    }

    int ng = w >> 1, fh = w & 1;
    int g = lane >> 2, tt = lane & 3;
    int tx = t & 31;
    int ty = t >> 5;
    float bias0 = b2[tx * 4], bias1 = b2[tx * 4 + 1];
    float bias2 = b2[tx * 4 + 2], bias3 = b2[tx * 4 + 3];
    __syncthreads();
    cudaGridDependencySynchronize();   // wait for k_agg2 (a2h)

    for (int tile = blockIdx.x; tile < nTiles; tile += gridDim.x) {
        int base = tile * MB;
        const unsigned* a2u = (const unsigned*)g_a2h;
        for (int i = t; i < MB * 32; i += 256) {
            int nl = i >> 5, c = i & 31;
            int nt = base + nl;
            unsigned v = (nt < n) ? a2u[nt * 32 + c] : 0u;
            *(unsigned*)&sA[nl * APAD + 2 * c] = v;
        }
        if (t < MB) {
            int nt = base + t;
            sB[t] = (nt < n) ? ld_idx(batch, nt, is64) : -1;
        }
        __syncthreads();

        float acc[8][4];
        #pragma unroll
        for (int nt = 0; nt < 8; nt++)
            #pragma unroll
            for (int q = 0; q < 4; q++) acc[nt][q] = 0.0f;

        #pragma unroll
        for (int ks = 0; ks < 4; ks++) {
            int k0 = ks * 16 + 2 * tt;
            const __half* arow0 = &sA[(ng * 16 + g) * APAD + k0];
            const __half* arow1 = arow0 + 8 * APAD;
            unsigned a0 = *(const unsigned*)arow0;
            unsigned a1 = *(const unsigned*)arow1;
            unsigned a2_ = *(const unsigned*)(arow0 + 8);
            unsigned a3 = *(const unsigned*)(arow1 + 8);
            #pragma unroll
            for (int nt = 0; nt < 8; nt++) {
                const __half* brow = &sW2T[(fh * 64 + nt * 8 + g) * APAD + k0];
                unsigned b0 = *(const unsigned*)brow;
                unsigned b1 = *(const unsigned*)(brow + 8);
                asm volatile(
                    "mma.sync.aligned.m16n8k16.row.col.f32.f16.f16.f32 "
                    "{%0,%1,%2,%3}, {%4,%5,%6,%7}, {%8,%9}, {%0,%1,%2,%3};"
                    : "+f"(acc[nt][0]), "+f"(acc[nt][1]), "+f"(acc[nt][2]), "+f"(acc[nt][3])
                    : "r"(a0), "r"(a1), "r"(a2_), "r"(a3), "r"(b0), "r"(b1));
            }
        }
        __syncthreads();

        #pragma unroll
        for (int nt = 0; nt < 8; nt++) {
            int row = ng * 16 + g;
            int col = fh * 64 + nt * 8 + 2 * tt;
            __half2 lo = __floats2half2_rn(acc[nt][0], acc[nt][1]);
            __half2 hi = __floats2half2_rn(acc[nt][2], acc[nt][3]);
            *(__half2*)&sC[row * CPAD + col] = lo;
            *(__half2*)&sC[(row + 8) * CPAD + col] = hi;
        }
        __syncthreads();

        int cur = -1;
        float run0 = 0, run1 = 0, run2 = 0, run3 = 0;
        #pragma unroll
        for (int q = 0; q < 8; q++) {
            int nl = ty * 8 + q;
            int gb = sB[nl];
            float2 v01 = __half22float2(*(const __half2*)&sC[nl * CPAD + 4 * tx]);
            float2 v23 = __half22float2(*(const __half2*)&sC[nl * CPAD + 4 * tx + 2]);
            float y0 = (gb >= 0) ? fmaxf(v01.x + bias0, 0.0f) : 0.0f;
            float y1v = (gb >= 0) ? fmaxf(v01.y + bias1, 0.0f) : 0.0f;
            float y2v = (gb >= 0) ? fmaxf(v23.x + bias2, 0.0f) : 0.0f;
            float y3 = (gb >= 0) ? fmaxf(v23.y + bias3, 0.0f) : 0.0f;
            if (gb != cur) {
                if (cur >= 0) {
                    float* p = &g_pool[cur * 128 + tx * 4];
                    atomicAdd(p, run0); atomicAdd(p + 1, run1);
                    atomicAdd(p + 2, run2); atomicAdd(p + 3, run3);
                }
                cur = gb; run0 = y0; run1 = y1v; run2 = y2v; run3 = y3;
            } else {
                run0 += y0; run1 += y1v; run2 += y2v; run3 += y3;
            }
        }
        if (cur >= 0) {
            float* p = &g_pool[cur * 128 + tx * 4];
            atomicAdd(p, run0); atomicAdd(p + 1, run1);
            atomicAdd(p + 2, run2); atomicAdd(p + 3, run3);
        }

        if (t == 0) {
            int rc = 0, cg = -1;
            for (int q = 0; q < MB; q++) {
                int gb = sB[q];
                if (gb != cg) {
                    if (cg >= 0) atomicAdd(&g_gcnt[cg], rc);
                    cg = gb; rc = (gb >= 0) ? 1 : 0;
                } else if (gb >= 0) rc++;
            }
            if (cg >= 0) atomicAdd(&g_gcnt[cg], rc);
        }
        __syncthreads();
    }
}

// ---------------- head: mean, fc1+relu, fc2 --------------------------------------
__global__ void k_head(const float* __restrict__ fc1W, const float* __restrict__ fc1b,
                       const float* __restrict__ fc2W, const float* __restrict__ fc2b,
                       float* __restrict__ out) {
    cudaGridDependencySynchronize();   // wait for k_gemm2pool (pool, gcnt)
    int g = blockIdx.x;
    int t = threadIdx.x;  // 128
    __shared__ float sv[128];
    __shared__ float red[64];
    float denom = fmaxf((float)g_gcnt[g], 1.0f);
    sv[t] = g_pool[g * 128 + t] / denom;
    __syncthreads();
    if (t < 64) {
        float a = fc1b[t];
        #pragma unroll 8
        for (int k = 0; k < 128; k++) a = fmaf(sv[k], fc1W[k * 64 + t], a);
        red[t] = fmaxf(a, 0.0f) * fc2W[t];
    }
    __syncthreads();
    if (t < 32) {
        float v = red[t] + red[t + 32];
        #pragma unroll
        for (int o = 16; o > 0; o >>= 1) v += __shfl_down_sync(0xffffffffu, v, o);
        if (t == 0) out[g] = v + fc2b[0];
    }
}

// ---------------- launch ----------------------------------------------------------
template <typename F, typename... Args>
static inline void launch_pdl(F f, dim3 grid, dim3 block, Args... args) {
    cudaLaunchConfig_t cfg = {};
    cfg.gridDim = grid;
    cfg.blockDim = block;
    cfg.stream = 0;
    cudaLaunchAttribute attr;
    attr.id = cudaLaunchAttributeProgrammaticStreamSerialization;
    attr.val.programmaticStreamSerializationAllowed = 1;
    cfg.attrs = &attr;
    cfg.numAttrs = 1;
    cudaLaunchKernelEx(&cfg, f, args...);
}

extern "C" void kernel_launch(void* const* d_in, const int* in_sizes, int n_in,
                              void* d_out, int out_size) {
    const float* x     = (const float*)d_in[0];
    const void*  ei    = d_in[1];
    const void*  batch = d_in[2];
    const float* W1    = (const float*)d_in[3];
    const float* b1    = (const float*)d_in[4];
    const float* W2    = (const float*)d_in[5];
    const float* b2    = (const float*)d_in[6];
    const float* fc1W  = (const float*)d_in[7];
    const float* fc1b  = (const float*)d_in[8];
    const float* fc2W  = (const float*)d_in[9];
    const float* fc2b  = (const float*)d_in[10];
    float* out = (float*)d_out;

    int N = in_sizes[0] / 4;   // 100000
    int E = in_sizes[1] / 2;   // 1600000

    k_zero<<<(32768 + 255) / 256, 256>>>((const unsigned int*)ei);

    int ep4 = (E + 3) / 4;  // edge quads
    launch_pdl(k_countfill, dim3((ep4 + 255) / 256), dim3(256), ei, E);

    launch_pdl(k_prep, dim3((N + 255) / 256), dim3(256), x, N);

    launch_pdl(k_l1, dim3(888), dim3(256), W1, b1, N);       // persistent, ~6/SM

    launch_pdl(k_agg2, dim3((N + 15) / 16), dim3(32, 16), N);

    int nTiles = (N + MB - 1) / MB;        // 1563
    launch_pdl(k_gemm2pool, dim3(521), dim3(256), W2, b2, batch, N, nTiles);

    launch_pdl(k_head, dim3(NG), dim3(128), fc1W, fc1b, fc2W, fc2b, out);
}